// round 2
// baseline (speedup 1.0000x reference)
#include <cuda_runtime.h>
#include <math.h>

// Problem constants (fixed by the dataset)
#define B_ 4
#define S_ 4096
#define D_ 1024
#define M_ (B_*S_)   // 16384

// GEMM tiling
#define BM 128
#define BN 128
#define BK 16
#define PAD 8
#define NCH 32       // S-chunks for k_sum reduction

// Scratch (no cudaMalloc allowed -> __device__ globals)
__device__ float g_q[(size_t)M_*D_];
__device__ float g_k[(size_t)M_*D_];
__device__ float g_v[(size_t)M_*D_];
__device__ float g_att[(size_t)M_*D_];
__device__ float g_kv[(size_t)B_*D_*D_];
__device__ float g_ksum[B_*D_];
__device__ float g_z[M_];

typedef unsigned long long ull;

static __device__ __forceinline__ ull pack2(float lo, float hi){
    ull r; asm("mov.b64 %0, {%1, %2};" : "=l"(r) : "f"(lo), "f"(hi)); return r;
}
static __device__ __forceinline__ void unpack2(ull v, float& lo, float& hi){
    asm("mov.b64 {%0, %1}, %2;" : "=f"(lo), "=f"(hi) : "l"(v));
}
// Blackwell packed fp32x2 FMA (FFMA2): 2x fp32 throughput vs scalar FFMA
static __device__ __forceinline__ void ffma2(ull& c, ull a, ull b){
    asm("fma.rn.f32x2 %0, %1, %2, %0;" : "+l"(c) : "l"(a), "l"(b));
}

// C[m,n] = sum_k opA(A)[m,k] * B[k,n]  (+bias)(+phi)(*z[m])(+resid)
// TRANSA=false: A row-major [M x K], lda = K
// TRANSA=true : A stored [K x M] row-major (lda = M-stride), i.e. C = A^T B
template<int ACT, bool HAS_Z, bool HAS_RES, bool TRANSA>
__global__ __launch_bounds__(256, 2)
void gemm_kernel(const float* __restrict__ Aall, long strideA,
                 const float* __restrict__ Ball, long strideB,
                 float* __restrict__ Call, long strideC,
                 const float* __restrict__ bias,
                 const float* __restrict__ Zall, long strideZ,
                 const float* __restrict__ Rall, long strideR,
                 int N, int K, int lda)
{
    const float* A  = Aall + (long)blockIdx.z * strideA;
    const float* Bw = Ball + (long)blockIdx.z * strideB;
    float*       C  = Call + (long)blockIdx.z * strideC;

    __shared__ float As[BK][BM + PAD];
    __shared__ float Bs[BK][BN];

    const int tid = threadIdx.x;
    const int tx = tid & 15;        // 0..15 -> 8 output cols each
    const int ty = tid >> 4;        // 0..15 -> 8 output rows each
    const long rowBase = (long)blockIdx.y * BM;
    const long colBase = (long)blockIdx.x * BN;

    float4 pa0, pa1, pb0, pb1;

    auto fetch = [&](int t){
        const int k0 = t * BK;
        if (TRANSA) {
            const int s0 = tid >> 5, c0 = (tid & 31) * 4;
            pa0 = *(const float4*)(A + (long)(k0 + s0    ) * lda + rowBase + c0);
            pa1 = *(const float4*)(A + (long)(k0 + s0 + 8) * lda + rowBase + c0);
        } else {
            const int r0 = tid >> 2, c0 = (tid & 3) * 4;
            pa0 = *(const float4*)(A + (rowBase + r0     ) * (long)lda + k0 + c0);
            pa1 = *(const float4*)(A + (rowBase + r0 + 64) * (long)lda + k0 + c0);
        }
        const int bs0 = tid >> 5, bc0 = (tid & 31) * 4;
        pb0 = *(const float4*)(Bw + (long)(k0 + bs0    ) * N + colBase + bc0);
        pb1 = *(const float4*)(Bw + (long)(k0 + bs0 + 8) * N + colBase + bc0);
    };
    auto store_smem = [&](){
        if (TRANSA) {
            const int s0 = tid >> 5, c0 = (tid & 31) * 4;
            *(float4*)&As[s0    ][c0] = pa0;
            *(float4*)&As[s0 + 8][c0] = pa1;
        } else {
            const int r0 = tid >> 2, c0 = (tid & 3) * 4;
            As[c0+0][r0] = pa0.x; As[c0+1][r0] = pa0.y;
            As[c0+2][r0] = pa0.z; As[c0+3][r0] = pa0.w;
            As[c0+0][r0+64] = pa1.x; As[c0+1][r0+64] = pa1.y;
            As[c0+2][r0+64] = pa1.z; As[c0+3][r0+64] = pa1.w;
        }
        const int bs0 = tid >> 5, bc0 = (tid & 31) * 4;
        *(float4*)&Bs[bs0    ][bc0] = pb0;
        *(float4*)&Bs[bs0 + 8][bc0] = pb1;
    };

    ull acc[8][4];
    #pragma unroll
    for (int j = 0; j < 8; ++j)
        #pragma unroll
        for (int i = 0; i < 4; ++i) acc[j][i] = 0ULL;

    const int nT = K / BK;
    fetch(0);
    for (int t = 0; t < nT; ++t) {
        store_smem();
        __syncthreads();
        if (t + 1 < nT) fetch(t + 1);   // prefetch next tile under compute

        #pragma unroll
        for (int k = 0; k < BK; ++k) {
            float4 a0 = *(const float4*)&As[k][ty * 8];
            float4 a1 = *(const float4*)&As[k][ty * 8 + 4];
            ulonglong2 b0 = *(const ulonglong2*)&Bs[k][tx * 8];
            ulonglong2 b1 = *(const ulonglong2*)&Bs[k][tx * 8 + 4];
            ull bp[4] = { b0.x, b0.y, b1.x, b1.y };
            float av[8] = { a0.x, a0.y, a0.z, a0.w, a1.x, a1.y, a1.z, a1.w };
            #pragma unroll
            for (int j = 0; j < 8; ++j) {
                ull aj = pack2(av[j], av[j]);
                #pragma unroll
                for (int i = 0; i < 4; ++i) ffma2(acc[j][i], aj, bp[i]);
            }
        }
        __syncthreads();
    }

    // Epilogue
    const long row0 = rowBase + ty * 8;
    const long col0 = colBase + tx * 8;
    float bv[8];
    #pragma unroll
    for (int i = 0; i < 8; ++i) bv[i] = bias ? bias[col0 + i] : 0.f;
    const float* Z = HAS_Z   ? (Zall + (long)blockIdx.z * strideZ) : nullptr;
    const float* R = HAS_RES ? (Rall + (long)blockIdx.z * strideR) : nullptr;

    #pragma unroll
    for (int j = 0; j < 8; ++j) {
        float o[8];
        #pragma unroll
        for (int i = 0; i < 4; ++i) unpack2(acc[j][i], o[2*i], o[2*i+1]);
        const long row = row0 + j;
        const float zs = HAS_Z ? Z[row] : 1.f;
        #pragma unroll
        for (int i = 0; i < 8; ++i) {
            float v2 = o[i] + bv[i];
            if (ACT == 1) v2 = (v2 > 0.f) ? (v2 + 1.f) : expf(v2);  // elu(x)+1
            if (HAS_Z)   v2 *= zs;
            if (HAS_RES) v2 += R[row * (long)N + col0 + i];
            o[i] = v2;
        }
        *(float4*)&C[row * (long)N + col0    ] = make_float4(o[0], o[1], o[2], o[3]);
        *(float4*)&C[row * (long)N + col0 + 4] = make_float4(o[4], o[5], o[6], o[7]);
    }
}

__global__ void zero_kernel(float* p, int n){
    int i = blockIdx.x * blockDim.x + threadIdx.x;
    if (i < n) p[i] = 0.f;
}

// k_sum[b,d] = sum_s k_phi[b,s,d]; parallelized over S-chunks with atomics
__global__ void ksum_kernel(const float* __restrict__ k, float* __restrict__ ksum){
    const int d  = blockIdx.x * blockDim.x + threadIdx.x;
    const int b  = blockIdx.y;
    const int ch = blockIdx.z;
    const int rows = S_ / NCH;
    const float* kp = k + ((long)b * S_ + (long)ch * rows) * D_ + d;
    float acc = 0.f;
    #pragma unroll 4
    for (int s = 0; s < rows; ++s) acc += kp[(long)s * D_];
    atomicAdd(&ksum[b * D_ + d], acc);
}

// z[b,s] = 1 / (q_phi[b,s,:] . ksum[b,:] + 1e-6)
__global__ void z_kernel(const float* __restrict__ q, const float* __restrict__ ksum,
                         float* __restrict__ z){
    const int s = blockIdx.x, b = blockIdx.y;
    const float4* qr = (const float4*)(q + ((long)b * S_ + s) * D_);
    const float4* kr = (const float4*)(ksum + (long)b * D_);
    float acc = 0.f;
    for (int i = threadIdx.x; i < D_ / 4; i += 128) {
        float4 a = qr[i], c = kr[i];
        acc += a.x * c.x + a.y * c.y + a.z * c.z + a.w * c.w;
    }
    #pragma unroll
    for (int o = 16; o > 0; o >>= 1) acc += __shfl_down_sync(0xffffffffu, acc, o);
    __shared__ float sm[4];
    if ((threadIdx.x & 31) == 0) sm[threadIdx.x >> 5] = acc;
    __syncthreads();
    if (threadIdx.x == 0) {
        float t = sm[0] + sm[1] + sm[2] + sm[3];
        z[(long)b * S_ + s] = 1.f / (t + 1e-6f);
    }
}

extern "C" void kernel_launch(void* const* d_in, const int* in_sizes, int n_in,
                              void* d_out, int out_size)
{
    const float* inputs  = (const float*)d_in[0];
    const float* context = (const float*)d_in[1];
    const float* Wq = (const float*)d_in[2]; const float* bq = (const float*)d_in[3];
    const float* Wk = (const float*)d_in[4]; const float* bk = (const float*)d_in[5];
    const float* Wv = (const float*)d_in[6]; const float* bv = (const float*)d_in[7];
    const float* Wo = (const float*)d_in[8]; const float* bo = (const float*)d_in[9];
    float* out = (float*)d_out;

    float *q, *k, *v, *att, *kv, *ksum, *z;
    cudaGetSymbolAddress((void**)&q,    g_q);
    cudaGetSymbolAddress((void**)&k,    g_k);
    cudaGetSymbolAddress((void**)&v,    g_v);
    cudaGetSymbolAddress((void**)&att,  g_att);
    cudaGetSymbolAddress((void**)&kv,   g_kv);
    cudaGetSymbolAddress((void**)&ksum, g_ksum);
    cudaGetSymbolAddress((void**)&z,    g_z);

    dim3 blk(256);
    dim3 gProj(D_ / BN, M_ / BM, 1);

    // q_phi = phi(inputs @ Wq + bq); k_phi = phi(context @ Wk + bk); v = context @ Wv + bv
    gemm_kernel<1,false,false,false><<<gProj, blk>>>(inputs, 0, Wq, 0, q, 0, bq,
                                                     nullptr, 0, nullptr, 0, D_, D_, D_);
    gemm_kernel<1,false,false,false><<<gProj, blk>>>(context, 0, Wk, 0, k, 0, bk,
                                                     nullptr, 0, nullptr, 0, D_, D_, D_);
    gemm_kernel<0,false,false,false><<<gProj, blk>>>(context, 0, Wv, 0, v, 0, bv,
                                                     nullptr, 0, nullptr, 0, D_, D_, D_);

    // k_sum and z
    zero_kernel<<<(B_ * D_ + 255) / 256, 256>>>(ksum, B_ * D_);
    ksum_kernel<<<dim3(D_ / 256, B_, NCH), 256>>>(k, ksum);
    z_kernel<<<dim3(S_, B_), 128>>>(q, ksum, z);

    // kv[b] = k_phi[b]^T @ v[b]   (TRANSA path: M=N=1024, K=4096)
    gemm_kernel<0,false,false,true><<<dim3(D_ / BN, D_ / BM, B_), blk>>>(
        k, (long)S_ * D_, v, (long)S_ * D_, kv, (long)D_ * D_,
        nullptr, nullptr, 0, nullptr, 0, D_, S_, D_);

    // att[b] = (q_phi[b] @ kv[b]) * z[b]
    gemm_kernel<0,true,false,false><<<dim3(D_ / BN, S_ / BM, B_), blk>>>(
        q, (long)S_ * D_, kv, (long)D_ * D_, att, (long)S_ * D_,
        nullptr, z, (long)S_, nullptr, 0, D_, D_, D_);

    // out = att @ Wo + bo + inputs
    gemm_kernel<0,false,true,false><<<gProj, blk>>>(att, 0, Wo, 0, out, 0, bo,
                                                    nullptr, 0, inputs, 0, D_, D_, D_);
}

// round 4
// speedup vs baseline: 2.3224x; 2.3224x over previous
#include <cuda_runtime.h>
#include <cuda_bf16.h>
#include <math.h>
#include <stdint.h>

// Problem constants
#define B_ 4
#define S_ 4096
#define D_ 1024
#define M_ (B_*S_)   // 16384

// ---------------- scratch (__device__ globals; no cudaMalloc allowed) ----------------
__device__ __nv_bfloat16 g_Xh[(size_t)M_*D_], g_Xl[(size_t)M_*D_];     // conv(inputs)
__device__ __nv_bfloat16 g_Ctxh[(size_t)M_*D_], g_Ctxl[(size_t)M_*D_]; // conv(context)
__device__ __nv_bfloat16 g_qh[(size_t)M_*D_], g_ql[(size_t)M_*D_];     // q_phi pair
__device__ float g_k[(size_t)M_*D_];                                   // k_phi fp32
__device__ float g_v[(size_t)M_*D_];                                   // v fp32
__device__ __nv_bfloat16 g_kTh[(size_t)M_*D_], g_kTl[(size_t)M_*D_];   // k_phi^T pair [B,D,S]
__device__ __nv_bfloat16 g_vTh[(size_t)M_*D_], g_vTl[(size_t)M_*D_];   // v^T pair [B,D,S]
__device__ float g_kv[(size_t)B_*D_*D_];                               // kv fp32 [B,D,D]
__device__ __nv_bfloat16 g_kvTh[(size_t)B_*D_*D_], g_kvTl[(size_t)B_*D_*D_]; // kv^T pair
__device__ __nv_bfloat16 g_atth[(size_t)M_*D_], g_attl[(size_t)M_*D_]; // att pair
__device__ __nv_bfloat16 g_Wqth[(size_t)D_*D_], g_Wqtl[(size_t)D_*D_];
__device__ __nv_bfloat16 g_Wkth[(size_t)D_*D_], g_Wktl[(size_t)D_*D_];
__device__ __nv_bfloat16 g_Wvth[(size_t)D_*D_], g_Wvtl[(size_t)D_*D_];
__device__ __nv_bfloat16 g_Woth[(size_t)D_*D_], g_Wotl[(size_t)D_*D_];
__device__ float g_ksum[B_*D_];
__device__ float g_z[M_];

// ---------------- PTX helpers (portable sm_80+ subset only; NO tcgen05) ----------------
static __device__ __forceinline__ uint32_t smem_u32(const void* p){
    uint32_t a;
    asm("{ .reg .u64 t; cvta.to.shared.u64 t, %1; cvt.u32.u64 %0, t; }" : "=r"(a) : "l"(p));
    return a;
}
static __device__ __forceinline__ void cp_async16(uint32_t dst, const void* src){
    asm volatile("cp.async.cg.shared.global [%0], [%1], 16;" :: "r"(dst), "l"(src) : "memory");
}
static __device__ __forceinline__ void cp_commit(){
    asm volatile("cp.async.commit_group;" ::: "memory");
}
template<int N>
static __device__ __forceinline__ void cp_wait(){
    asm volatile("cp.async.wait_group %0;" :: "n"(N) : "memory");
}
static __device__ __forceinline__ void ldsm4(uint32_t* r, uint32_t addr){
    asm volatile("ldmatrix.sync.aligned.m8n8.x4.shared.b16 {%0,%1,%2,%3}, [%4];"
                 : "=r"(r[0]), "=r"(r[1]), "=r"(r[2]), "=r"(r[3]) : "r"(addr));
}
static __device__ __forceinline__ void mma16816(float* d, const uint32_t* a, const uint32_t* b){
    asm volatile("mma.sync.aligned.m16n8k16.row.col.f32.bf16.bf16.f32 "
                 "{%0,%1,%2,%3}, {%4,%5,%6,%7}, {%8,%9}, {%0,%1,%2,%3};"
                 : "+f"(d[0]), "+f"(d[1]), "+f"(d[2]), "+f"(d[3])
                 : "r"(a[0]), "r"(a[1]), "r"(a[2]), "r"(a[3]), "r"(b[0]), "r"(b[1]));
}

// SMEM: stage = Ah 16K | Al 16K | Bh 16K | Bl 16K = 64KB; double-buffered = 128KB
#define STAGE_BYTES 65536
#define SMEM_TOTAL  (2*STAGE_BYTES)

// ---------------- HMMA GEMM: C[m,n] = sum_k A[m,k]*B[n,k] ----------------
// A = Ah+Al, B = Bh+Bl (bf16 split, BOTH K-major), K % 64 == 0.
// 128x128 CTA tile, 8 warps in 2x4, warp tile 64x32, 3-pass split (AhBh + AlBh + AhBl).
template<int ACT, bool HAS_Z, bool HAS_RES, bool PAIR>
__global__ __launch_bounds__(256, 1)
void mma_gemm(const __nv_bfloat16* __restrict__ Ahg, const __nv_bfloat16* __restrict__ Alg, long sA,
              const __nv_bfloat16* __restrict__ Bhg, const __nv_bfloat16* __restrict__ Blg, long sB,
              float* __restrict__ Cf, __nv_bfloat16* __restrict__ Cph, __nv_bfloat16* __restrict__ Cpl,
              long sC,
              const float* __restrict__ bias,
              const float* __restrict__ Zall, long sZ,
              const float* __restrict__ Rall, long sR,
              int N, int K)
{
    extern __shared__ char smem[];
    const uint32_t sbase = smem_u32(smem);
    const int tid  = threadIdx.x;
    const int wid  = tid >> 5;
    const int lane = tid & 31;
    const int warp_m = wid >> 2;      // 0..1 -> 64 rows
    const int warp_n = wid & 3;       // 0..3 -> 32 cols

    const __nv_bfloat16* Ah = Ahg + (long)blockIdx.z * sA;
    const __nv_bfloat16* Al = Alg + (long)blockIdx.z * sA;
    const __nv_bfloat16* Bh = Bhg + (long)blockIdx.z * sB;
    const __nv_bfloat16* Bl = Blg + (long)blockIdx.z * sB;
    const long rowBase = (long)blockIdx.y * 128;
    const long colBase = (long)blockIdx.x * 128;

    // ---- stage loader: 4 subtiles, each 128 rows x 64 bf16, XOR-swizzled 16B chunks ----
    auto load_stage = [&](int t, int s){
        const long k0 = (long)t * 64;
        const uint32_t dstbase = sbase + (uint32_t)s * STAGE_BYTES;
        const __nv_bfloat16* srcs[4] = {
            Ah + rowBase * K + k0, Al + rowBase * K + k0,
            Bh + colBase * K + k0, Bl + colBase * K + k0 };
        #pragma unroll
        for (int sub = 0; sub < 4; ++sub){
            const __nv_bfloat16* sp = srcs[sub];
            const uint32_t db = dstbase + sub * 16384;
            #pragma unroll
            for (int j = 0; j < 4; ++j){
                const int id  = tid + j * 256;       // 0..1023 chunk id
                const int row = id >> 3, c = id & 7;
                const uint32_t daddr = db + (((row << 3) + (c ^ (row & 7))) << 4);
                cp_async16(daddr, sp + (long)row * K + c * 8);
            }
        }
    };

    float acc[4][4][4];
    #pragma unroll
    for (int a = 0; a < 4; ++a)
        #pragma unroll
        for (int b = 0; b < 4; ++b)
            #pragma unroll
            for (int c = 0; c < 4; ++c) acc[a][b][c] = 0.f;

    const int r16 = lane & 15, cs = lane >> 4;   // ldmatrix addressing

    auto compute_stage = [&](int s){
        const uint32_t st = sbase + (uint32_t)s * STAGE_BYTES;
        #pragma unroll
        for (int kk = 0; kk < 4; ++kk){
            const int kc = kk * 2 + cs;          // 16B chunk index along k (k0/8 + cs)
            uint32_t ah[4][4], al[4][4], bh[4][2], bl[4][2];
            #pragma unroll
            for (int mf = 0; mf < 4; ++mf){
                const int row = warp_m * 64 + mf * 16 + r16;
                const uint32_t off = ((row << 3) + (kc ^ (row & 7))) << 4;
                ldsm4(ah[mf], st + off);            // Ah subtile at +0
                ldsm4(al[mf], st + 16384 + off);    // Al subtile
            }
            #pragma unroll
            for (int p = 0; p < 2; ++p){
                const int row = warp_n * 32 + p * 16 + r16;
                const uint32_t off = ((row << 3) + (kc ^ (row & 7))) << 4;
                uint32_t t0[4], t1[4];
                ldsm4(t0, st + 32768 + off);        // Bh
                ldsm4(t1, st + 49152 + off);        // Bl
                bh[p*2+0][0] = t0[0]; bh[p*2+1][0] = t0[1];
                bh[p*2+0][1] = t0[2]; bh[p*2+1][1] = t0[3];
                bl[p*2+0][0] = t1[0]; bl[p*2+1][0] = t1[1];
                bl[p*2+0][1] = t1[2]; bl[p*2+1][1] = t1[3];
            }
            #pragma unroll
            for (int mf = 0; mf < 4; ++mf)
                #pragma unroll
                for (int nf = 0; nf < 4; ++nf) mma16816(acc[mf][nf], ah[mf], bh[nf]);
            #pragma unroll
            for (int mf = 0; mf < 4; ++mf)
                #pragma unroll
                for (int nf = 0; nf < 4; ++nf) mma16816(acc[mf][nf], al[mf], bh[nf]);
            #pragma unroll
            for (int mf = 0; mf < 4; ++mf)
                #pragma unroll
                for (int nf = 0; nf < 4; ++nf) mma16816(acc[mf][nf], ah[mf], bl[nf]);
        }
    };

    const int nT = K / 64;
    load_stage(0, 0);
    cp_commit();
    for (int t = 0; t < nT; ++t){
        if (t + 1 < nT){
            load_stage(t + 1, (t + 1) & 1);
            cp_commit();
            cp_wait<1>();
        } else {
            cp_wait<0>();
        }
        __syncthreads();
        compute_stage(t & 1);
        __syncthreads();
    }

    // ---- epilogue ----
    const int gr = lane >> 2, gc = (lane & 3) * 2;
    const float* Z = HAS_Z   ? (Zall + (long)blockIdx.z * sZ) : nullptr;
    const float* R = HAS_RES ? (Rall + (long)blockIdx.z * sR) : nullptr;

    #pragma unroll
    for (int mf = 0; mf < 4; ++mf){
        #pragma unroll
        for (int h = 0; h < 2; ++h){
            const long row = rowBase + warp_m * 64 + mf * 16 + gr + h * 8;
            const float zs = HAS_Z ? Z[row] : 1.f;
            #pragma unroll
            for (int nf = 0; nf < 4; ++nf){
                const long col = colBase + warp_n * 32 + nf * 8 + gc;
                float v0 = acc[mf][nf][h*2+0];
                float v1 = acc[mf][nf][h*2+1];
                if (bias){ v0 += bias[col]; v1 += bias[col+1]; }
                if (ACT == 1){
                    v0 = (v0 > 0.f) ? (v0 + 1.f) : __expf(v0);
                    v1 = (v1 > 0.f) ? (v1 + 1.f) : __expf(v1);
                }
                if (HAS_Z){ v0 *= zs; v1 *= zs; }
                if (HAS_RES){
                    float2 rr = *(const float2*)(R + row * (long)N + col);
                    v0 += rr.x; v1 += rr.y;
                }
                if (PAIR){
                    __nv_bfloat16 h0 = __float2bfloat16(v0);
                    __nv_bfloat16 h1 = __float2bfloat16(v1);
                    __nv_bfloat162 hp; hp.x = h0; hp.y = h1;
                    __nv_bfloat162 lp;
                    lp.x = __float2bfloat16(v0 - __bfloat162float(h0));
                    lp.y = __float2bfloat16(v1 - __bfloat162float(h1));
                    *(__nv_bfloat162*)((Cph + (long)blockIdx.z * sC) + row * (long)N + col) = hp;
                    *(__nv_bfloat162*)((Cpl + (long)blockIdx.z * sC) + row * (long)N + col) = lp;
                } else {
                    *(float2*)((Cf + (long)blockIdx.z * sC) + row * (long)N + col) = make_float2(v0, v1);
                }
            }
        }
    }
}

// ---------------- convert fp32 -> bf16 hi/lo (same layout) ----------------
__global__ __launch_bounds__(256)
void conv_kernel(const float* __restrict__ in, __nv_bfloat16* __restrict__ hi,
                 __nv_bfloat16* __restrict__ lo, int n4)
{
    int i = blockIdx.x * 256 + threadIdx.x;
    if (i >= n4) return;
    float4 x = ((const float4*)in)[i];
    __nv_bfloat162 h0, h1, l0, l1;
    h0.x = __float2bfloat16(x.x); h0.y = __float2bfloat16(x.y);
    h1.x = __float2bfloat16(x.z); h1.y = __float2bfloat16(x.w);
    l0.x = __float2bfloat16(x.x - __bfloat162float(h0.x));
    l0.y = __float2bfloat16(x.y - __bfloat162float(h0.y));
    l1.x = __float2bfloat16(x.z - __bfloat162float(h1.x));
    l1.y = __float2bfloat16(x.w - __bfloat162float(h1.y));
    ((__nv_bfloat162*)hi)[2*i]   = h0; ((__nv_bfloat162*)hi)[2*i+1] = h1;
    ((__nv_bfloat162*)lo)[2*i]   = l0; ((__nv_bfloat162*)lo)[2*i+1] = l1;
}

// ---------------- transpose + convert: fp32 [R,C] -> bf16 hi/lo [C,R] ----------------
__global__ __launch_bounds__(256)
void tconv_kernel(const float* __restrict__ in, long inStride,
                  __nv_bfloat16* __restrict__ oh, __nv_bfloat16* __restrict__ ol,
                  long outStride, int R, int C)
{
    __shared__ float t[32][33];
    const float* src = in + (long)blockIdx.z * inStride;
    __nv_bfloat16* dh = oh + (long)blockIdx.z * outStride;
    __nv_bfloat16* dl = ol + (long)blockIdx.z * outStride;
    const int x = blockIdx.x * 32, y = blockIdx.y * 32;
    #pragma unroll
    for (int j = 0; j < 4; ++j)
        t[threadIdx.y + 8*j][threadIdx.x] = src[(long)(y + threadIdx.y + 8*j) * C + x + threadIdx.x];
    __syncthreads();
    #pragma unroll
    for (int j = 0; j < 4; ++j){
        float v = t[threadIdx.x][threadIdx.y + 8*j];
        __nv_bfloat16 h = __float2bfloat16(v);
        __nv_bfloat16 l = __float2bfloat16(v - __bfloat162float(h));
        long o = (long)(x + threadIdx.y + 8*j) * R + y + threadIdx.x;
        dh[o] = h; dl[o] = l;
    }
}

// ---------------- k_sum / z ----------------
__global__ void zero_kernel(float* p, int n){
    int i = blockIdx.x * blockDim.x + threadIdx.x;
    if (i < n) p[i] = 0.f;
}
#define NCH 32
__global__ void ksum_kernel(const float* __restrict__ k, float* __restrict__ ksum){
    const int d  = blockIdx.x * blockDim.x + threadIdx.x;
    const int b  = blockIdx.y;
    const int ch = blockIdx.z;
    const int rows = S_ / NCH;
    const float* kp = k + ((long)b * S_ + (long)ch * rows) * D_ + d;
    float acc = 0.f;
    #pragma unroll 4
    for (int s = 0; s < rows; ++s) acc += kp[(long)s * D_];
    atomicAdd(&ksum[b * D_ + d], acc);
}
__global__ void z_kernel(const __nv_bfloat16* __restrict__ qh, const __nv_bfloat16* __restrict__ ql,
                         const float* __restrict__ ksum, float* __restrict__ z)
{
    const int s = blockIdx.x, b = blockIdx.y;
    const __nv_bfloat162* q2h = (const __nv_bfloat162*)(qh + ((long)b * S_ + s) * D_);
    const __nv_bfloat162* q2l = (const __nv_bfloat162*)(ql + ((long)b * S_ + s) * D_);
    const float2* k2 = (const float2*)(ksum + (long)b * D_);
    float acc = 0.f;
    for (int i = threadIdx.x; i < D_ / 2; i += 128){
        __nv_bfloat162 h = q2h[i], l = q2l[i];
        float2 kk = k2[i];
        acc += (__bfloat162float(h.x) + __bfloat162float(l.x)) * kk.x
             + (__bfloat162float(h.y) + __bfloat162float(l.y)) * kk.y;
    }
    #pragma unroll
    for (int o = 16; o > 0; o >>= 1) acc += __shfl_down_sync(0xffffffffu, acc, o);
    __shared__ float sm[4];
    if ((threadIdx.x & 31) == 0) sm[threadIdx.x >> 5] = acc;
    __syncthreads();
    if (threadIdx.x == 0)
        z[(long)b * S_ + s] = 1.f / (sm[0] + sm[1] + sm[2] + sm[3] + 1e-6f);
}

// ---------------- launcher ----------------
extern "C" void kernel_launch(void* const* d_in, const int* in_sizes, int n_in,
                              void* d_out, int out_size)
{
    const float* inputs  = (const float*)d_in[0];
    const float* context = (const float*)d_in[1];
    const float* Wq = (const float*)d_in[2]; const float* bq = (const float*)d_in[3];
    const float* Wk = (const float*)d_in[4]; const float* bk = (const float*)d_in[5];
    const float* Wv = (const float*)d_in[6]; const float* bv = (const float*)d_in[7];
    const float* Wo = (const float*)d_in[8]; const float* bo = (const float*)d_in[9];
    float* out = (float*)d_out;

    __nv_bfloat16 *Xh,*Xl,*Ch,*Cl,*qh,*ql,*kTh,*kTl,*vTh,*vTl,*kvTh,*kvTl,*atth,*attl;
    __nv_bfloat16 *Wqth,*Wqtl,*Wkth,*Wktl,*Wvth,*Wvtl,*Woth,*Wotl;
    float *kf,*vf,*kvf,*ksum,*z;
    cudaGetSymbolAddress((void**)&Xh, g_Xh);     cudaGetSymbolAddress((void**)&Xl, g_Xl);
    cudaGetSymbolAddress((void**)&Ch, g_Ctxh);   cudaGetSymbolAddress((void**)&Cl, g_Ctxl);
    cudaGetSymbolAddress((void**)&qh, g_qh);     cudaGetSymbolAddress((void**)&ql, g_ql);
    cudaGetSymbolAddress((void**)&kf, g_k);      cudaGetSymbolAddress((void**)&vf, g_v);
    cudaGetSymbolAddress((void**)&kTh, g_kTh);   cudaGetSymbolAddress((void**)&kTl, g_kTl);
    cudaGetSymbolAddress((void**)&vTh, g_vTh);   cudaGetSymbolAddress((void**)&vTl, g_vTl);
    cudaGetSymbolAddress((void**)&kvf, g_kv);
    cudaGetSymbolAddress((void**)&kvTh, g_kvTh); cudaGetSymbolAddress((void**)&kvTl, g_kvTl);
    cudaGetSymbolAddress((void**)&atth, g_atth); cudaGetSymbolAddress((void**)&attl, g_attl);
    cudaGetSymbolAddress((void**)&Wqth, g_Wqth); cudaGetSymbolAddress((void**)&Wqtl, g_Wqtl);
    cudaGetSymbolAddress((void**)&Wkth, g_Wkth); cudaGetSymbolAddress((void**)&Wktl, g_Wktl);
    cudaGetSymbolAddress((void**)&Wvth, g_Wvth); cudaGetSymbolAddress((void**)&Wvtl, g_Wvtl);
    cudaGetSymbolAddress((void**)&Woth, g_Woth); cudaGetSymbolAddress((void**)&Wotl, g_Wotl);
    cudaGetSymbolAddress((void**)&ksum, g_ksum); cudaGetSymbolAddress((void**)&z, g_z);

    // opt-in to 128 KB dynamic smem for all GEMM instantiations
    cudaFuncSetAttribute(mma_gemm<1,false,false,true >, cudaFuncAttributeMaxDynamicSharedMemorySize, SMEM_TOTAL);
    cudaFuncSetAttribute(mma_gemm<1,false,false,false>, cudaFuncAttributeMaxDynamicSharedMemorySize, SMEM_TOTAL);
    cudaFuncSetAttribute(mma_gemm<0,false,false,false>, cudaFuncAttributeMaxDynamicSharedMemorySize, SMEM_TOTAL);
    cudaFuncSetAttribute(mma_gemm<0,true ,false,true >, cudaFuncAttributeMaxDynamicSharedMemorySize, SMEM_TOTAL);
    cudaFuncSetAttribute(mma_gemm<0,false,true ,false>, cudaFuncAttributeMaxDynamicSharedMemorySize, SMEM_TOTAL);

    const long MD = (long)M_ * D_;
    const long SD = (long)S_ * D_;
    const long DD = (long)D_ * D_;

    // 1) convert activations to bf16 pairs
    conv_kernel<<<(int)(MD/4/256), 256>>>(inputs,  Xh, Xl, (int)(MD/4));
    conv_kernel<<<(int)(MD/4/256), 256>>>(context, Ch, Cl, (int)(MD/4));

    // 2) transpose-convert weights: [K,N] -> [N,K] pairs
    dim3 tb(32, 8);
    dim3 tgW(D_/32, D_/32, 1);
    tconv_kernel<<<tgW, tb>>>(Wq, 0, Wqth, Wqtl, 0, D_, D_);
    tconv_kernel<<<tgW, tb>>>(Wk, 0, Wkth, Wktl, 0, D_, D_);
    tconv_kernel<<<tgW, tb>>>(Wv, 0, Wvth, Wvtl, 0, D_, D_);
    tconv_kernel<<<tgW, tb>>>(Wo, 0, Woth, Wotl, 0, D_, D_);

    dim3 blk(256);
    dim3 gProj(D_/128, M_/128, 1);

    // 3) projections
    mma_gemm<1,false,false,true ><<<gProj, blk, SMEM_TOTAL>>>(
        Xh, Xl, 0, Wqth, Wqtl, 0, nullptr, qh, ql, 0, bq, nullptr, 0, nullptr, 0, D_, D_);
    mma_gemm<1,false,false,false><<<gProj, blk, SMEM_TOTAL>>>(
        Ch, Cl, 0, Wkth, Wktl, 0, kf, nullptr, nullptr, 0, bk, nullptr, 0, nullptr, 0, D_, D_);
    mma_gemm<0,false,false,false><<<gProj, blk, SMEM_TOTAL>>>(
        Ch, Cl, 0, Wvth, Wvtl, 0, vf, nullptr, nullptr, 0, bv, nullptr, 0, nullptr, 0, D_, D_);

    // 4) k_sum and z
    zero_kernel<<<(B_*D_ + 255)/256, 256>>>(ksum, B_*D_);
    ksum_kernel<<<dim3(D_/256, B_, NCH), 256>>>(kf, ksum);
    z_kernel<<<dim3(S_, B_), 128>>>(qh, ql, ksum, z);

    // 5) transpose-convert k_phi, v: [S,D] -> [D,S] pairs per batch
    dim3 tgKV(D_/32, S_/32, B_);
    tconv_kernel<<<tgKV, tb>>>(kf, SD, kTh, kTl, SD, S_, D_);
    tconv_kernel<<<tgKV, tb>>>(vf, SD, vTh, vTl, SD, S_, D_);

    // 6) kv[b] = k^T v : A=[D,S] pair, B=v^T [D,S] pair, K=S
    mma_gemm<0,false,false,false><<<dim3(D_/128, D_/128, B_), blk, SMEM_TOTAL>>>(
        kTh, kTl, SD, vTh, vTl, SD, kvf, nullptr, nullptr, DD,
        nullptr, nullptr, 0, nullptr, 0, D_, S_);

    // 7) transpose-convert kv: [D,D] -> [D,D] pairs
    dim3 tgKv2(D_/32, D_/32, B_);
    tconv_kernel<<<tgKv2, tb>>>(kvf, DD, kvTh, kvTl, DD, D_, D_);

    // 8) att[b] = (q kv) * z : A=q pair [S,D], B=kv^T pair [D,D]
    mma_gemm<0,true,false,true><<<dim3(D_/128, S_/128, B_), blk, SMEM_TOTAL>>>(
        qh, ql, SD, kvTh, kvTl, DD, nullptr, atth, attl, SD,
        nullptr, z, (long)S_, nullptr, 0, D_, D_);

    // 9) out = att Wo + bo + inputs
    mma_gemm<0,false,true,false><<<gProj, blk, SMEM_TOTAL>>>(
        atth, attl, 0, Woth, Wotl, 0, out, nullptr, nullptr, 0,
        bo, nullptr, 0, inputs, 0, D_, D_);
}

// round 5
// speedup vs baseline: 2.3999x; 1.0334x over previous
#include <cuda_runtime.h>
#include <cuda_bf16.h>
#include <math.h>
#include <stdint.h>

// Problem constants
#define B_ 4
#define S_ 4096
#define D_ 1024
#define M_ (B_*S_)   // 16384

// ---------------- scratch (__device__ globals; no cudaMalloc allowed) ----------------
__device__ __nv_bfloat16 g_Xh[(size_t)M_*D_], g_Xl[(size_t)M_*D_];     // conv(inputs)
__device__ __nv_bfloat16 g_Ctxh[(size_t)M_*D_], g_Ctxl[(size_t)M_*D_]; // conv(context)
__device__ __nv_bfloat16 g_qh[(size_t)M_*D_], g_ql[(size_t)M_*D_];     // q_phi pair [B*S, D]
__device__ __nv_bfloat16 g_kTh[(size_t)M_*D_], g_kTl[(size_t)M_*D_];   // k_phi^T pair [B,D,S]
__device__ __nv_bfloat16 g_vTh[(size_t)M_*D_], g_vTl[(size_t)M_*D_];   // v^T pair [B,D,S]
__device__ __nv_bfloat16 g_kvTh[(size_t)B_*D_*D_], g_kvTl[(size_t)B_*D_*D_]; // kv^T pair [B,E,D]
__device__ __nv_bfloat16 g_atth[(size_t)M_*D_], g_attl[(size_t)M_*D_]; // att pair [B*S, D]
__device__ __nv_bfloat16 g_Wqth[(size_t)D_*D_], g_Wqtl[(size_t)D_*D_];
__device__ __nv_bfloat16 g_Wkth[(size_t)D_*D_], g_Wktl[(size_t)D_*D_];
__device__ __nv_bfloat16 g_Wvth[(size_t)D_*D_], g_Wvtl[(size_t)D_*D_];
__device__ __nv_bfloat16 g_Woth[(size_t)D_*D_], g_Wotl[(size_t)D_*D_];
__device__ float g_ksum[B_*D_];
__device__ float g_z[M_];

// ---------------- PTX helpers (portable sm_80+ subset only; NO tcgen05) ----------------
static __device__ __forceinline__ uint32_t smem_u32(const void* p){
    uint32_t a;
    asm("{ .reg .u64 t; cvta.to.shared.u64 t, %1; cvt.u32.u64 %0, t; }" : "=r"(a) : "l"(p));
    return a;
}
static __device__ __forceinline__ void cp_async16(uint32_t dst, const void* src){
    asm volatile("cp.async.cg.shared.global [%0], [%1], 16;" :: "r"(dst), "l"(src) : "memory");
}
static __device__ __forceinline__ void cp_commit(){
    asm volatile("cp.async.commit_group;" ::: "memory");
}
template<int N>
static __device__ __forceinline__ void cp_wait(){
    asm volatile("cp.async.wait_group %0;" :: "n"(N) : "memory");
}
static __device__ __forceinline__ void ldsm4(uint32_t* r, uint32_t addr){
    asm volatile("ldmatrix.sync.aligned.m8n8.x4.shared.b16 {%0,%1,%2,%3}, [%4];"
                 : "=r"(r[0]), "=r"(r[1]), "=r"(r[2]), "=r"(r[3]) : "r"(addr));
}
static __device__ __forceinline__ void mma16816(float* d, const uint32_t* a, const uint32_t* b){
    asm volatile("mma.sync.aligned.m16n8k16.row.col.f32.bf16.bf16.f32 "
                 "{%0,%1,%2,%3}, {%4,%5,%6,%7}, {%8,%9}, {%0,%1,%2,%3};"
                 : "+f"(d[0]), "+f"(d[1]), "+f"(d[2]), "+f"(d[3])
                 : "r"(a[0]), "r"(a[1]), "r"(a[2]), "r"(a[3]), "r"(b[0]), "r"(b[1]));
}

// SMEM: stage = Ah 16K | Al 16K | Bh 16K | Bl 16K = 64KB; double-buffered = 128KB
#define STAGE_BYTES 65536
#define SMEM_TOTAL  (2*STAGE_BYTES)

// Output modes
#define OUT_F32   0
#define OUT_PAIR  1
#define OUT_PAIRT 2

// ---------------- HMMA GEMM: C[m,n] = sum_k A[m,k]*B[n,k] ----------------
// A = Ah+Al, B = Bh+Bl (bf16 split, BOTH K-major), K % 64 == 0.
// 128x128 CTA tile, 8 warps 2x4, warp tile 64x32, 3-pass split (AhBh + AlBh + AhBl).
// OUT_PAIRT: writes C^T as bf16 hi/lo pairs: out[b][n][m_local], b = (m>>rowShift),
//            m_local = m & rowMask, row stride ldT, per-batch stride sBatchT.
template<int ACT, bool HAS_Z, bool HAS_RES, int OUT>
__global__ __launch_bounds__(256, 1)
void mma_gemm(const __nv_bfloat16* __restrict__ Ahg, const __nv_bfloat16* __restrict__ Alg, long sA,
              const __nv_bfloat16* __restrict__ Bhg, const __nv_bfloat16* __restrict__ Blg, long sB,
              float* __restrict__ Cf, __nv_bfloat16* __restrict__ Cph, __nv_bfloat16* __restrict__ Cpl,
              long sC,
              const float* __restrict__ bias,
              const float* __restrict__ Zall, long sZ,
              const float* __restrict__ Rall, long sR,
              int N, int K,
              long sBatchT, int ldT, int rowShift, int rowMask)
{
    extern __shared__ char smem[];
    const uint32_t sbase = smem_u32(smem);
    const int tid  = threadIdx.x;
    const int wid  = tid >> 5;
    const int lane = tid & 31;
    const int warp_m = wid >> 2;      // 0..1 -> 64 rows
    const int warp_n = wid & 3;       // 0..3 -> 32 cols

    const __nv_bfloat16* Ah = Ahg + (long)blockIdx.z * sA;
    const __nv_bfloat16* Al = Alg + (long)blockIdx.z * sA;
    const __nv_bfloat16* Bh = Bhg + (long)blockIdx.z * sB;
    const __nv_bfloat16* Bl = Blg + (long)blockIdx.z * sB;
    const long rowBase = (long)blockIdx.y * 128;
    const long colBase = (long)blockIdx.x * 128;

    // ---- stage loader: 4 subtiles, each 128 rows x 64 bf16, XOR-swizzled 16B chunks ----
    auto load_stage = [&](int t, int s){
        const long k0 = (long)t * 64;
        const uint32_t dstbase = sbase + (uint32_t)s * STAGE_BYTES;
        const __nv_bfloat16* srcs[4] = {
            Ah + rowBase * K + k0, Al + rowBase * K + k0,
            Bh + colBase * K + k0, Bl + colBase * K + k0 };
        #pragma unroll
        for (int sub = 0; sub < 4; ++sub){
            const __nv_bfloat16* sp = srcs[sub];
            const uint32_t db = dstbase + sub * 16384;
            #pragma unroll
            for (int j = 0; j < 4; ++j){
                const int id  = tid + j * 256;       // 0..1023 chunk id
                const int row = id >> 3, c = id & 7;
                const uint32_t daddr = db + (((row << 3) + (c ^ (row & 7))) << 4);
                cp_async16(daddr, sp + (long)row * K + c * 8);
            }
        }
    };

    float acc[4][4][4];
    #pragma unroll
    for (int a = 0; a < 4; ++a)
        #pragma unroll
        for (int b = 0; b < 4; ++b)
            #pragma unroll
            for (int c = 0; c < 4; ++c) acc[a][b][c] = 0.f;

    const int r16 = lane & 15, cs = lane >> 4;   // ldmatrix addressing

    // double-buffered fragments
    uint32_t ah[2][4][4], al[2][4][4], bh[2][4][2], bl[2][4][2];

    auto load_frags = [&](uint32_t st, int kk, int buf){
        const int kc = kk * 2 + cs;              // 16B chunk index along k
        #pragma unroll
        for (int mf = 0; mf < 4; ++mf){
            const int row = warp_m * 64 + mf * 16 + r16;
            const uint32_t off = ((row << 3) + (kc ^ (row & 7))) << 4;
            ldsm4(ah[buf][mf], st + off);            // Ah subtile at +0
            ldsm4(al[buf][mf], st + 16384 + off);    // Al subtile
        }
        #pragma unroll
        for (int p = 0; p < 2; ++p){
            const int row = warp_n * 32 + p * 16 + r16;
            const uint32_t off = ((row << 3) + (kc ^ (row & 7))) << 4;
            uint32_t t0[4], t1[4];
            ldsm4(t0, st + 32768 + off);             // Bh
            ldsm4(t1, st + 49152 + off);             // Bl
            bh[buf][p*2+0][0] = t0[0]; bh[buf][p*2+1][0] = t0[1];
            bh[buf][p*2+0][1] = t0[2]; bh[buf][p*2+1][1] = t0[3];
            bl[buf][p*2+0][0] = t1[0]; bl[buf][p*2+1][0] = t1[1];
            bl[buf][p*2+0][1] = t1[2]; bl[buf][p*2+1][1] = t1[3];
        }
    };

    const int nT = K / 64;
    load_stage(0, 0);
    cp_commit();
    cp_wait<0>();
    __syncthreads();
    uint32_t stc = sbase;
    load_frags(stc, 0, 0);

    for (int t = 0; t < nT; ++t){
        if (t + 1 < nT){ load_stage(t + 1, (t + 1) & 1); cp_commit(); }
        #pragma unroll
        for (int kk = 0; kk < 4; ++kk){
            const int cb = kk & 1;
            if (kk < 3) load_frags(stc, kk + 1, cb ^ 1);  // prefetch next k-step frags
            #pragma unroll
            for (int mf = 0; mf < 4; ++mf)
                #pragma unroll
                for (int nf = 0; nf < 4; ++nf) mma16816(acc[mf][nf], ah[cb][mf], bh[cb][nf]);
            #pragma unroll
            for (int mf = 0; mf < 4; ++mf)
                #pragma unroll
                for (int nf = 0; nf < 4; ++nf) mma16816(acc[mf][nf], al[cb][mf], bh[cb][nf]);
            #pragma unroll
            for (int mf = 0; mf < 4; ++mf)
                #pragma unroll
                for (int nf = 0; nf < 4; ++nf) mma16816(acc[mf][nf], ah[cb][mf], bl[cb][nf]);
        }
        if (t + 1 < nT){
            cp_wait<0>();
            __syncthreads();
            stc = sbase + (uint32_t)((t + 1) & 1) * STAGE_BYTES;
            load_frags(stc, 0, 0);
        }
    }

    // ---- epilogue ----
    const int gr = lane >> 2, gc = (lane & 3) * 2;
    const float* Z = HAS_Z   ? (Zall + (long)blockIdx.z * sZ) : nullptr;
    const float* R = HAS_RES ? (Rall + (long)blockIdx.z * sR) : nullptr;

    if (OUT == OUT_PAIRT){
        __syncthreads();   // all warps done reading stage SMEM before reuse as transpose tile
        float* ts = (float*)smem;   // 128 x 132 fp32
        #pragma unroll
        for (int mf = 0; mf < 4; ++mf){
            #pragma unroll
            for (int h = 0; h < 2; ++h){
                const int rl = warp_m * 64 + mf * 16 + gr + h * 8;
                #pragma unroll
                for (int nf = 0; nf < 4; ++nf){
                    const int cl = warp_n * 32 + nf * 8 + gc;
                    float v0 = acc[mf][nf][h*2+0];
                    float v1 = acc[mf][nf][h*2+1];
                    if (bias){ v0 += bias[colBase + cl]; v1 += bias[colBase + cl + 1]; }
                    if (ACT == 1){
                        v0 = (v0 > 0.f) ? (v0 + 1.f) : __expf(v0);
                        v1 = (v1 > 0.f) ? (v1 + 1.f) : __expf(v1);
                    }
                    ts[rl * 132 + cl]     = v0;
                    ts[rl * 132 + cl + 1] = v1;
                }
            }
        }
        __syncthreads();
        // write transposed pairs: out row n = tid>>1 (0..127), 64 m each
        const int r   = tid >> 1;
        const int seg = (tid & 1) * 64;
        const int bb  = (int)((rowBase + seg) >> rowShift);
        const long mo = (rowBase + seg) & rowMask;
        __nv_bfloat16* dh = Cph + (long)blockIdx.z * sC + (long)bb * sBatchT
                          + (colBase + r) * (long)ldT + mo;
        __nv_bfloat16* dl = Cpl + (long)blockIdx.z * sC + (long)bb * sBatchT
                          + (colBase + r) * (long)ldT + mo;
        #pragma unroll
        for (int j = 0; j < 64; j += 2){
            float x0 = ts[(seg + j    ) * 132 + r];
            float x1 = ts[(seg + j + 1) * 132 + r];
            __nv_bfloat16 h0 = __float2bfloat16(x0);
            __nv_bfloat16 h1 = __float2bfloat16(x1);
            __nv_bfloat162 hp; hp.x = h0; hp.y = h1;
            __nv_bfloat162 lp;
            lp.x = __float2bfloat16(x0 - __bfloat162float(h0));
            lp.y = __float2bfloat16(x1 - __bfloat162float(h1));
            *(__nv_bfloat162*)(dh + j) = hp;
            *(__nv_bfloat162*)(dl + j) = lp;
        }
        return;
    }

    #pragma unroll
    for (int mf = 0; mf < 4; ++mf){
        #pragma unroll
        for (int h = 0; h < 2; ++h){
            const long row = rowBase + warp_m * 64 + mf * 16 + gr + h * 8;
            const float zs = HAS_Z ? Z[row] : 1.f;
            #pragma unroll
            for (int nf = 0; nf < 4; ++nf){
                const long col = colBase + warp_n * 32 + nf * 8 + gc;
                float v0 = acc[mf][nf][h*2+0];
                float v1 = acc[mf][nf][h*2+1];
                if (bias){ v0 += bias[col]; v1 += bias[col+1]; }
                if (ACT == 1){
                    v0 = (v0 > 0.f) ? (v0 + 1.f) : __expf(v0);
                    v1 = (v1 > 0.f) ? (v1 + 1.f) : __expf(v1);
                }
                if (HAS_Z){ v0 *= zs; v1 *= zs; }
                if (HAS_RES){
                    float2 rr = *(const float2*)(R + row * (long)N + col);
                    v0 += rr.x; v1 += rr.y;
                }
                if (OUT == OUT_PAIR){
                    __nv_bfloat16 h0 = __float2bfloat16(v0);
                    __nv_bfloat16 h1 = __float2bfloat16(v1);
                    __nv_bfloat162 hp; hp.x = h0; hp.y = h1;
                    __nv_bfloat162 lp;
                    lp.x = __float2bfloat16(v0 - __bfloat162float(h0));
                    lp.y = __float2bfloat16(v1 - __bfloat162float(h1));
                    *(__nv_bfloat162*)((Cph + (long)blockIdx.z * sC) + row * (long)N + col) = hp;
                    *(__nv_bfloat162*)((Cpl + (long)blockIdx.z * sC) + row * (long)N + col) = lp;
                } else {
                    *(float2*)((Cf + (long)blockIdx.z * sC) + row * (long)N + col) = make_float2(v0, v1);
                }
            }
        }
    }
}

// ---------------- convert fp32 -> bf16 hi/lo (same layout) ----------------
__global__ __launch_bounds__(256)
void conv_kernel(const float* __restrict__ in, __nv_bfloat16* __restrict__ hi,
                 __nv_bfloat16* __restrict__ lo, int n4)
{
    int i = blockIdx.x * 256 + threadIdx.x;
    if (i >= n4) return;
    float4 x = ((const float4*)in)[i];
    __nv_bfloat162 h0, h1, l0, l1;
    h0.x = __float2bfloat16(x.x); h0.y = __float2bfloat16(x.y);
    h1.x = __float2bfloat16(x.z); h1.y = __float2bfloat16(x.w);
    l0.x = __float2bfloat16(x.x - __bfloat162float(h0.x));
    l0.y = __float2bfloat16(x.y - __bfloat162float(h0.y));
    l1.x = __float2bfloat16(x.z - __bfloat162float(h1.x));
    l1.y = __float2bfloat16(x.w - __bfloat162float(h1.y));
    ((__nv_bfloat162*)hi)[2*i]   = h0; ((__nv_bfloat162*)hi)[2*i+1] = h1;
    ((__nv_bfloat162*)lo)[2*i]   = l0; ((__nv_bfloat162*)lo)[2*i+1] = l1;
}

// ---------------- fused weight transpose+convert: 4x fp32 [D,D] -> bf16 hi/lo [D,D]^T ----------------
__global__ __launch_bounds__(256)
void wtconv_kernel(const float* __restrict__ W0, const float* __restrict__ W1,
                   const float* __restrict__ W2, const float* __restrict__ W3,
                   __nv_bfloat16* __restrict__ h0, __nv_bfloat16* __restrict__ l0,
                   __nv_bfloat16* __restrict__ h1, __nv_bfloat16* __restrict__ l1,
                   __nv_bfloat16* __restrict__ h2, __nv_bfloat16* __restrict__ l2,
                   __nv_bfloat16* __restrict__ h3, __nv_bfloat16* __restrict__ l3)
{
    __shared__ float t[32][33];
    const float* src; __nv_bfloat16 *dh, *dl;
    switch (blockIdx.z){
        case 0:  src = W0; dh = h0; dl = l0; break;
        case 1:  src = W1; dh = h1; dl = l1; break;
        case 2:  src = W2; dh = h2; dl = l2; break;
        default: src = W3; dh = h3; dl = l3; break;
    }
    const int x = blockIdx.x * 32, y = blockIdx.y * 32;
    #pragma unroll
    for (int j = 0; j < 4; ++j)
        t[threadIdx.y + 8*j][threadIdx.x] = src[(long)(y + threadIdx.y + 8*j) * D_ + x + threadIdx.x];
    __syncthreads();
    #pragma unroll
    for (int j = 0; j < 4; ++j){
        float v = t[threadIdx.x][threadIdx.y + 8*j];
        __nv_bfloat16 h = __float2bfloat16(v);
        __nv_bfloat16 l = __float2bfloat16(v - __bfloat162float(h));
        long o = (long)(x + threadIdx.y + 8*j) * D_ + y + threadIdx.x;
        dh[o] = h; dl[o] = l;
    }
}

// ---------------- ksum from kT pairs: ksum[b*D+d] = sum_s (h+l)[b,d,s] ----------------
__global__ __launch_bounds__(256)
void ksumT_kernel(const __nv_bfloat16* __restrict__ kTh, const __nv_bfloat16* __restrict__ kTl,
                  float* __restrict__ ksum)
{
    const int row  = blockIdx.x * 8 + (threadIdx.x >> 5);   // 0..4095
    const int lane = threadIdx.x & 31;
    const __nv_bfloat162* h2 = (const __nv_bfloat162*)(kTh + (long)row * S_);
    const __nv_bfloat162* l2 = (const __nv_bfloat162*)(kTl + (long)row * S_);
    float acc = 0.f;
    #pragma unroll 4
    for (int i = lane; i < S_/2; i += 32){
        __nv_bfloat162 h = h2[i], l = l2[i];
        acc += __bfloat162float(h.x) + __bfloat162float(h.y)
             + __bfloat162float(l.x) + __bfloat162float(l.y);
    }
    #pragma unroll
    for (int o = 16; o > 0; o >>= 1) acc += __shfl_down_sync(0xffffffffu, acc, o);
    if (lane == 0) ksum[row] = acc;
}

// ---------------- z[b,s] = 1/(q_phi . ksum + 1e-6) ----------------
__global__ void z_kernel(const __nv_bfloat16* __restrict__ qh, const __nv_bfloat16* __restrict__ ql,
                         const float* __restrict__ ksum, float* __restrict__ z)
{
    const int s = blockIdx.x, b = blockIdx.y;
    const __nv_bfloat162* q2h = (const __nv_bfloat162*)(qh + ((long)b * S_ + s) * D_);
    const __nv_bfloat162* q2l = (const __nv_bfloat162*)(ql + ((long)b * S_ + s) * D_);
    const float2* k2 = (const float2*)(ksum + (long)b * D_);
    float acc = 0.f;
    for (int i = threadIdx.x; i < D_ / 2; i += 128){
        __nv_bfloat162 h = q2h[i], l = q2l[i];
        float2 kk = k2[i];
        acc += (__bfloat162float(h.x) + __bfloat162float(l.x)) * kk.x
             + (__bfloat162float(h.y) + __bfloat162float(l.y)) * kk.y;
    }
    #pragma unroll
    for (int o = 16; o > 0; o >>= 1) acc += __shfl_down_sync(0xffffffffu, acc, o);
    __shared__ float sm[4];
    if ((threadIdx.x & 31) == 0) sm[threadIdx.x >> 5] = acc;
    __syncthreads();
    if (threadIdx.x == 0)
        z[(long)b * S_ + s] = 1.f / (sm[0] + sm[1] + sm[2] + sm[3] + 1e-6f);
}

// ---------------- launcher ----------------
extern "C" void kernel_launch(void* const* d_in, const int* in_sizes, int n_in,
                              void* d_out, int out_size)
{
    const float* inputs  = (const float*)d_in[0];
    const float* context = (const float*)d_in[1];
    const float* Wq = (const float*)d_in[2]; const float* bq = (const float*)d_in[3];
    const float* Wk = (const float*)d_in[4]; const float* bk = (const float*)d_in[5];
    const float* Wv = (const float*)d_in[6]; const float* bv = (const float*)d_in[7];
    const float* Wo = (const float*)d_in[8]; const float* bo = (const float*)d_in[9];
    float* out = (float*)d_out;

    __nv_bfloat16 *Xh,*Xl,*Ch,*Cl,*qh,*ql,*kTh,*kTl,*vTh,*vTl,*kvTh,*kvTl,*atth,*attl;
    __nv_bfloat16 *Wqth,*Wqtl,*Wkth,*Wktl,*Wvth,*Wvtl,*Woth,*Wotl;
    float *ksum,*z;
    cudaGetSymbolAddress((void**)&Xh, g_Xh);     cudaGetSymbolAddress((void**)&Xl, g_Xl);
    cudaGetSymbolAddress((void**)&Ch, g_Ctxh);   cudaGetSymbolAddress((void**)&Cl, g_Ctxl);
    cudaGetSymbolAddress((void**)&qh, g_qh);     cudaGetSymbolAddress((void**)&ql, g_ql);
    cudaGetSymbolAddress((void**)&kTh, g_kTh);   cudaGetSymbolAddress((void**)&kTl, g_kTl);
    cudaGetSymbolAddress((void**)&vTh, g_vTh);   cudaGetSymbolAddress((void**)&vTl, g_vTl);
    cudaGetSymbolAddress((void**)&kvTh, g_kvTh); cudaGetSymbolAddress((void**)&kvTl, g_kvTl);
    cudaGetSymbolAddress((void**)&atth, g_atth); cudaGetSymbolAddress((void**)&attl, g_attl);
    cudaGetSymbolAddress((void**)&Wqth, g_Wqth); cudaGetSymbolAddress((void**)&Wqtl, g_Wqtl);
    cudaGetSymbolAddress((void**)&Wkth, g_Wkth); cudaGetSymbolAddress((void**)&Wktl, g_Wktl);
    cudaGetSymbolAddress((void**)&Wvth, g_Wvth); cudaGetSymbolAddress((void**)&Wvtl, g_Wvtl);
    cudaGetSymbolAddress((void**)&Woth, g_Woth); cudaGetSymbolAddress((void**)&Wotl, g_Wotl);
    cudaGetSymbolAddress((void**)&ksum, g_ksum); cudaGetSymbolAddress((void**)&z, g_z);

    // opt-in to 128 KB dynamic smem for all GEMM instantiations
    cudaFuncSetAttribute(mma_gemm<1,false,false,OUT_PAIR >, cudaFuncAttributeMaxDynamicSharedMemorySize, SMEM_TOTAL);
    cudaFuncSetAttribute(mma_gemm<1,false,false,OUT_PAIRT>, cudaFuncAttributeMaxDynamicSharedMemorySize, SMEM_TOTAL);
    cudaFuncSetAttribute(mma_gemm<0,false,false,OUT_PAIRT>, cudaFuncAttributeMaxDynamicSharedMemorySize, SMEM_TOTAL);
    cudaFuncSetAttribute(mma_gemm<0,true ,false,OUT_PAIR >, cudaFuncAttributeMaxDynamicSharedMemorySize, SMEM_TOTAL);
    cudaFuncSetAttribute(mma_gemm<0,false,true ,OUT_F32  >, cudaFuncAttributeMaxDynamicSharedMemorySize, SMEM_TOTAL);

    const long MD = (long)M_ * D_;
    const long SD = (long)S_ * D_;
    const long DD = (long)D_ * D_;

    dim3 blk(256);
    dim3 tb(32, 8);
    dim3 gProj(D_/128, M_/128, 1);

    // launch 0,1: convert activations to bf16 pairs
    conv_kernel<<<(int)(MD/4/256), 256>>>(inputs,  Xh, Xl, (int)(MD/4));
    conv_kernel<<<(int)(MD/4/256), 256>>>(context, Ch, Cl, (int)(MD/4));

    // launch 2: all 4 weight transposes fused
    wtconv_kernel<<<dim3(D_/32, D_/32, 4), tb>>>(Wq, Wk, Wv, Wo,
        Wqth, Wqtl, Wkth, Wktl, Wvth, Wvtl, Woth, Wotl);

    // launch 3: q_phi = phi(inputs Wq + bq) -> pair [B*S, D]
    mma_gemm<1,false,false,OUT_PAIR><<<gProj, blk, SMEM_TOTAL>>>(
        Xh, Xl, 0, Wqth, Wqtl, 0, nullptr, qh, ql, 0, bq,
        nullptr, 0, nullptr, 0, D_, D_, 0, 0, 0, 0);

    // launch 4: k_phi = phi(context Wk + bk) -> TRANSPOSED pair [B, D, S]
    mma_gemm<1,false,false,OUT_PAIRT><<<gProj, blk, SMEM_TOTAL>>>(
        Ch, Cl, 0, Wkth, Wktl, 0, nullptr, kTh, kTl, 0, bk,
        nullptr, 0, nullptr, 0, D_, D_, (long)D_*S_, S_, 12, S_-1);

    // launch 5 (ncu capture target): v = context Wv + bv -> TRANSPOSED pair [B, D, S]
    mma_gemm<0,false,false,OUT_PAIRT><<<gProj, blk, SMEM_TOTAL>>>(
        Ch, Cl, 0, Wvth, Wvtl, 0, nullptr, vTh, vTl, 0, bv,
        nullptr, 0, nullptr, 0, D_, D_, (long)D_*S_, S_, 12, S_-1);

    // launch 6,7: k_sum and z
    ksumT_kernel<<<(B_*D_)/8, 256>>>(kTh, kTl, ksum);
    z_kernel<<<dim3(S_, B_), 128>>>(qh, ql, ksum, z);

    // launch 8: kv[b] = k^T v (A=kT [D,S], B=vT [D,S], K=S) -> TRANSPOSED pair kvT [B, E, D]
    mma_gemm<0,false,false,OUT_PAIRT><<<dim3(D_/128, D_/128, B_), blk, SMEM_TOTAL>>>(
        kTh, kTl, SD, vTh, vTl, SD, nullptr, kvTh, kvTl, DD,
        nullptr, nullptr, 0, nullptr, 0, D_, S_, 0, D_, 30, D_-1);

    // launch 9: att[b] = (q kv) * z (A=q pair [S,D], B=kvT pair [E,D]) -> pair [B*S, D]
    mma_gemm<0,true,false,OUT_PAIR><<<dim3(D_/128, S_/128, B_), blk, SMEM_TOTAL>>>(
        qh, ql, SD, kvTh, kvTl, DD, nullptr, atth, attl, SD,
        nullptr, z, (long)S_, nullptr, 0, D_, D_, 0, 0, 0, 0);

    // launch 10: out = att Wo + bo + inputs (fp32)
    mma_gemm<0,false,true,OUT_F32><<<gProj, blk, SMEM_TOTAL>>>(
        atth, attl, 0, Woth, Wotl, 0, out, nullptr, nullptr, 0,
        bo, nullptr, 0, inputs, 0, D_, D_, 0, 0, 0, 0);
}